// round 16
// baseline (speedup 1.0000x reference)
#include <cuda_runtime.h>
#include <cstdint>

#define BATCH    8
#define CHANNELS 512
#define SPATIAL  1024
#define NHEADS   8
#define HDIM     64
#define GCH      64
#define NBH      (BATCH*NHEADS)
#define BC       (CHANNELS*SPATIAL)

// -------- scratch --------
__device__ uint16_t g_xnT[BATCH*BC];             // bf16 [b][p][c]
__device__ uint16_t g_qT [BATCH*BC];             // bf16 [b][p][c] (scale*log2e folded)
__device__ uint16_t g_kT [BATCH*BC];             // bf16 [b][p][c]
__device__ uint16_t g_v  [BATCH*BC];             // bf16 [b][c][p]
__device__ uint16_t g_aoT[BATCH*BC];             // bf16 [b][p][c]
__device__ uint16_t g_w[4][CHANNELS*CHANNELS];   // bf16 [o][c]
__device__ float    g_b[4][CHANNELS];

// ---------------- helpers ----------------
__device__ __forceinline__ uint32_t packbf(float lo, float hi) {
    uint32_t r;
    asm("cvt.rn.bf16x2.f32 %0, %1, %2;" : "=r"(r) : "f"(hi), "f"(lo));
    return r;
}
__device__ __forceinline__ uint16_t bf16u(float x) {
    uint16_t u;
    asm("cvt.rn.bf16.f32 %0, %1;" : "=h"(u) : "f"(x));
    return u;
}
__device__ __forceinline__ float ex2(float x) {
    float r;
    asm("ex2.approx.ftz.f32 %0, %1;" : "=f"(r) : "f"(x));
    return r;
}
__device__ __forceinline__ void mma16(float* c, const uint32_t* a, const uint32_t* b) {
    asm volatile("mma.sync.aligned.m16n8k16.row.col.f32.bf16.bf16.f32 "
        "{%0,%1,%2,%3}, {%4,%5,%6,%7}, {%8,%9}, {%0,%1,%2,%3};"
        : "+f"(c[0]), "+f"(c[1]), "+f"(c[2]), "+f"(c[3])
        : "r"(a[0]), "r"(a[1]), "r"(a[2]), "r"(a[3]), "r"(b[0]), "r"(b[1]));
}
__device__ __forceinline__ void ldm4(uint32_t* r, uint32_t saddr) {
    asm volatile("ldmatrix.sync.aligned.m8n8.x4.shared.b16 {%0,%1,%2,%3}, [%4];"
        : "=r"(r[0]), "=r"(r[1]), "=r"(r[2]), "=r"(r[3]) : "r"(saddr));
}
__device__ __forceinline__ void cp16b(uint16_t* s, const uint16_t* g) {
    uint32_t sa = (uint32_t)__cvta_generic_to_shared(s);
    asm volatile("cp.async.cg.shared.global [%0], [%1], 16;" :: "r"(sa), "l"(g));
}
#define CP_COMMIT() asm volatile("cp.async.commit_group;" ::: "memory")
#define CP_WAIT(N)  asm volatile("cp.async.wait_group %0;" :: "n"(N) : "memory")

// ============================================================================
// GroupNorm fused with transpose+bf16 (double-buffered tile, 1 sync/iter)
// ============================================================================
__global__ __launch_bounds__(512) void gnT_kernel(const float* __restrict__ x,
                                                  const float* __restrict__ w,
                                                  const float* __restrict__ bgn) {
    int bg = blockIdx.x;
    int b = bg >> 3, g = bg & 7;
    size_t base = (size_t)(b*CHANNELS + g*GCH) * SPATIAL;
    const float4* x4 = (const float4*)(x + base);
    int tid = threadIdx.x;

    float s = 0.f, ss = 0.f;
    for (int i = tid; i < GCH*SPATIAL/4; i += 512) {
        float4 v = x4[i];
        s  += v.x + v.y + v.z + v.w;
        ss += v.x*v.x + v.y*v.y + v.z*v.z + v.w*v.w;
    }
    __shared__ float rs[512], rq[512];
    rs[tid] = s; rq[tid] = ss;
    __syncthreads();
    for (int o = 256; o > 0; o >>= 1) {
        if (tid < o) { rs[tid] += rs[tid+o]; rq[tid] += rq[tid+o]; }
        __syncthreads();
    }
    float mu  = rs[0] * (1.f/65536.f);
    float var = rq[0] * (1.f/65536.f) - mu*mu;
    float rstd = rsqrtf(var + 1e-5f);

    __shared__ float tile[2][GCH][33];
    int cl = tid >> 3, p4 = (tid & 7) * 4;
    float wc = w[g*GCH + cl] * rstd;
    float bc = bgn[g*GCH + cl] - mu*wc;
    int pw = tid >> 4, c4 = (tid & 15) * 4;

    // prologue: fill tile 0
    {
        float4 v = *(const float4*)&x[base + (size_t)cl*SPATIAL + p4];
        tile[0][cl][p4    ] = v.x*wc + bc;
        tile[0][cl][p4 + 1] = v.y*wc + bc;
        tile[0][cl][p4 + 2] = v.z*wc + bc;
        tile[0][cl][p4 + 3] = v.w*wc + bc;
    }
    for (int pt = 0; pt < 32; pt++) {
        int cur = pt & 1;
        __syncthreads();   // tile[cur] writes visible; tile[cur^1] reads (pt-1) done
        if (pt < 31) {
            int pB1 = (pt+1) * 32;
            float4 v = *(const float4*)&x[base + (size_t)cl*SPATIAL + pB1 + p4];
            tile[cur^1][cl][p4    ] = v.x*wc + bc;
            tile[cur^1][cl][p4 + 1] = v.y*wc + bc;
            tile[cur^1][cl][p4 + 2] = v.z*wc + bc;
            tile[cur^1][cl][p4 + 3] = v.w*wc + bc;
        }
        int pB = pt * 32;
        uint2 o;
        o.x = packbf(tile[cur][c4  ][pw], tile[cur][c4+1][pw]);
        o.y = packbf(tile[cur][c4+2][pw], tile[cur][c4+3][pw]);
        *(uint2*)&g_xnT[((size_t)b*SPATIAL + pB + pw)*CHANNELS + g*GCH + c4] = o;
    }
}

// ============================================================================
// Weight/bias prep. Q gets 0.125*log2(e) folded (exp2-domain softmax).
// ============================================================================
#define QSCALE (0.125f * 1.44269504f)

__global__ __launch_bounds__(256) void wprep(const float* __restrict__ qw, const float* __restrict__ kw,
                                             const float* __restrict__ vw, const float* __restrict__ pw,
                                             const float* __restrict__ qb, const float* __restrict__ kb,
                                             const float* __restrict__ vb, const float* __restrict__ pb) {
    int g = blockIdx.x*256 + threadIdx.x;
    if (g < 4*131072) {
        int m = g >> 17, r = g & 131071;
        const float* src = m == 0 ? qw : m == 1 ? kw : m == 2 ? vw : pw;
        float sc = (m == 0) ? QSCALE : 1.f;
        float2 v = *(const float2*)&src[(size_t)r*2];
        ((uint32_t*)g_w[m])[r] = packbf(v.x*sc, v.y*sc);
    } else {
        int gb = g - 4*131072;
        if (gb < 2048) {
            int m = gb >> 9, o = gb & 511;
            const float* src = m == 0 ? qb : m == 1 ? kb : m == 2 ? vb : pb;
            g_b[m][o] = src[o] * ((m == 0) ? QSCALE : 1.f);
        }
    }
}

// ============================================================================
// Conv1x1 bf16 m16n8k16 + ldmatrix, Kt=64, 2-buffer / 1-barrier-per-iter.
// ============================================================================
#define CSTG 9216
#define CONV_SMEM (4*CSTG*2)   // 73728 B

__device__ __forceinline__ void conv_stage_bf(uint16_t* sA, uint16_t* sB,
                                              const uint16_t* W, const uint16_t* Xt,
                                              int k0, int tid) {
    #pragma unroll
    for (int q = 0; q < 4; q++) {
        int i = tid + q*256;
        int row = i >> 3, c = (i & 7) * 8;
        cp16b(&sA[row*72 + c], &W[(size_t)row*CHANNELS + k0 + c]);
    }
    #pragma unroll
    for (int q = 0; q < 4; q++) {
        int i = tid + q*256;
        int row = i >> 3, c = (i & 7) * 8;
        cp16b(&sB[row*72 + c], &Xt[(size_t)row*CHANNELS + k0 + c]);
    }
}

__device__ __forceinline__ void conv_core_bf(const uint16_t* __restrict__ W,
                                             const float* __restrict__ bias,
                                             const uint16_t* __restrict__ Xt,
                                             int mode,
                                             uint16_t* __restrict__ outT,
                                             uint16_t* __restrict__ outD,
                                             float* __restrict__ outF,
                                             const float* __restrict__ resid) {
    extern __shared__ __align__(16) uint16_t csm[];
    int tid = threadIdx.x, lane = tid & 31, wid = tid >> 5;
    int wy = wid & 3, wx = wid >> 2;
    int lq = lane >> 2, lr = lane & 3;

    uint32_t aoff = (lane & 15)*144 + (lane >> 4)*16;
    uint32_t boff = (lane & 7)*144 + ((lane >> 3) & 1)*16 + (lane >> 4)*1152;

    float acc[2][8][4];
    #pragma unroll
    for (int i = 0; i < 2; i++)
        #pragma unroll
        for (int j = 0; j < 8; j++)
            #pragma unroll
            for (int t = 0; t < 4; t++) acc[i][j][t] = 0.f;

    conv_stage_bf(csm, csm + 2*CSTG, W, Xt, 0, tid);
    CP_COMMIT();

    for (int it = 0; it < 8; it++) {
        int cur = it & 1;
        CP_WAIT(0);
        __syncthreads();
        if (it < 7) {
            conv_stage_bf(csm + (cur^1)*CSTG, csm + (2 + (cur^1))*CSTG,
                          W, Xt, (it+1)*64, tid);
            CP_COMMIT();
        }

        uint32_t sAa = (uint32_t)__cvta_generic_to_shared(csm + cur*CSTG);
        uint32_t sBa = (uint32_t)__cvta_generic_to_shared(csm + (2+cur)*CSTG);
        #pragma unroll
        for (int ks = 0; ks < 4; ks++) {
            uint32_t a[2][4], b[4][4];
            #pragma unroll
            for (int mi = 0; mi < 2; mi++)
                ldm4(a[mi], sAa + (wy*32 + mi*16)*144 + ks*32 + aoff);
            #pragma unroll
            for (int pp = 0; pp < 4; pp++)
                ldm4(b[pp], sBa + (wx*64 + pp*16)*144 + ks*32 + boff);
            #pragma unroll
            for (int mi = 0; mi < 2; mi++)
                #pragma unroll
                for (int pp = 0; pp < 4; pp++) {
                    mma16(acc[mi][2*pp],   a[mi], &b[pp][0]);
                    mma16(acc[mi][2*pp+1], a[mi], &b[pp][2]);
                }
        }
    }

    if (mode == 2) {
        #pragma unroll
        for (int mi = 0; mi < 2; mi++) {
            int o0 = wy*32 + mi*16 + lq;
            float bi0 = bias[o0], bi8 = bias[o0+8];
            #pragma unroll
            for (int ni = 0; ni < 8; ni++) {
                int p = wx*64 + ni*8 + lr*2;
                size_t off0 = (size_t)o0*SPATIAL + p;
                size_t off8 = (size_t)(o0+8)*SPATIAL + p;
                float2 r0 = make_float2(acc[mi][ni][0] + bi0, acc[mi][ni][1] + bi0);
                float2 r8 = make_float2(acc[mi][ni][2] + bi8, acc[mi][ni][3] + bi8);
                float2 v0 = *(const float2*)&resid[off0];
                float2 v8 = *(const float2*)&resid[off8];
                r0.x += v0.x; r0.y += v0.y;
                r8.x += v8.x; r8.y += v8.y;
                *(float2*)&outF[off0] = r0;
                *(float2*)&outF[off8] = r8;
            }
        }
    } else if (mode == 1) {
        #pragma unroll
        for (int mi = 0; mi < 2; mi++) {
            int o0 = wy*32 + mi*16 + lq;
            float bi0 = bias[o0], bi8 = bias[o0+8];
            uint32_t* r0 = (uint32_t*)(outD + (size_t)o0*SPATIAL);
            uint32_t* r8 = (uint32_t*)(outD + (size_t)(o0+8)*SPATIAL);
            #pragma unroll
            for (int ni = 0; ni < 8; ni++) {
                int pc = wx*32 + ni*4 + lr;
                r0[pc] = packbf(acc[mi][ni][0] + bi0, acc[mi][ni][1] + bi0);
                r8[pc] = packbf(acc[mi][ni][2] + bi8, acc[mi][ni][3] + bi8);
            }
        }
    } else {
        __syncthreads();
        uint16_t* Ts = csm;   // [128 p][136]
        #pragma unroll
        for (int mi = 0; mi < 2; mi++) {
            int o0 = wy*32 + mi*16 + lq;
            float bi0 = bias[o0], bi8 = bias[o0+8];
            #pragma unroll
            for (int ni = 0; ni < 8; ni++) {
                int p = wx*64 + ni*8 + lr*2;
                Ts[(p  )*136 + o0    ] = bf16u(acc[mi][ni][0] + bi0);
                Ts[(p+1)*136 + o0    ] = bf16u(acc[mi][ni][1] + bi0);
                Ts[(p  )*136 + o0 + 8] = bf16u(acc[mi][ni][2] + bi8);
                Ts[(p+1)*136 + o0 + 8] = bf16u(acc[mi][ni][3] + bi8);
            }
        }
        __syncthreads();
        #pragma unroll
        for (int q = 0; q < 8; q++) {
            int i = tid + q*256;
            int p = i >> 4, c = (i & 15) * 8;
            *(uint4*)&outT[(size_t)p*CHANNELS + c] = *(uint4*)&Ts[p*136 + c];
        }
    }
}

__global__ __launch_bounds__(256, 2) void conv_qkv_bf() {
    int b = blockIdx.z;
    int sel = blockIdx.y >> 2;
    int oB = (blockIdx.y & 3) * 128;
    int pB = blockIdx.x * 128;
    const uint16_t* W = g_w[sel] + (size_t)oB*CHANNELS;
    const float* bias = g_b[sel] + oB;
    const uint16_t* Xt = g_xnT + ((size_t)b*SPATIAL + pB)*CHANNELS;
    if (sel == 2) {
        conv_core_bf(W, bias, Xt, 1, nullptr,
                     g_v + (size_t)b*BC + (size_t)oB*SPATIAL + pB, nullptr, nullptr);
    } else {
        uint16_t* gT = (sel == 0) ? g_qT : g_kT;
        conv_core_bf(W, bias, Xt, 0,
                     gT + (size_t)b*BC + (size_t)pB*CHANNELS + oB,
                     nullptr, nullptr, nullptr);
    }
}

__global__ __launch_bounds__(256, 2) void conv_proj_bf(const float* __restrict__ x,
                                                       float* __restrict__ out) {
    int b = blockIdx.z, oB = blockIdx.y*128, pB = blockIdx.x*128;
    conv_core_bf(g_w[3] + (size_t)oB*CHANNELS, g_b[3] + oB,
                 g_aoT + ((size_t)b*SPATIAL + pB)*CHANNELS, 2,
                 nullptr, nullptr,
                 out + (size_t)b*BC + (size_t)oB*SPATIAL + pB,
                 x + (size_t)b*BC + (size_t)oB*SPATIAL + pB);
}

// ============================================================================
// Flash bf16, m-tile 128, exp2 softmax, alpha-skip, Q fragments hoisted.
// smem halves: Q[128][72] | K0[128][72] | K1 | V0[64][136] | V1
// ============================================================================
#define FQ  0
#define FK0 9216
#define FK1 18432
#define FV0 27648
#define FV1 36352
#define FL_SMEM (45056 * 2)   // 90112 B

__global__ __launch_bounds__(256, 2) void flash_bf() {
    extern __shared__ __align__(16) uint16_t fsm[];
    int nB = blockIdx.x * 128;
    int bh = blockIdx.y;
    int b = bh >> 3, h = bh & 7;
    const uint16_t* qT = g_qT + (size_t)b*BC + h*HDIM;
    const uint16_t* kT = g_kT + (size_t)b*BC + h*HDIM;
    const uint16_t* vB = g_v  + (size_t)b*BC + (size_t)h*HDIM*SPATIAL;
    uint16_t* aoT      = g_aoT + (size_t)b*BC + h*HDIM;

    int tid = threadIdx.x, lane = tid & 31, wid = tid >> 5;
    int lq = lane >> 2, lr = lane & 3;
    int n0 = wid * 16;

    uint32_t aoff  = (lane & 15)*144 + (lane >> 4)*16;
    uint32_t boff  = (lane & 7)*144 + ((lane >> 3) & 1)*16 + (lane >> 4)*1152;
    uint32_t vboff = (lane & 7)*272 + ((lane >> 3) & 1)*16 + (lane >> 4)*2176;

    // stage Q + K0/V0
    #pragma unroll
    for (int q = 0; q < 4; q++) {
        int i = tid + q*256;
        int row = i >> 3, c = (i & 7) * 8;
        cp16b(&fsm[FQ + row*72 + c], &qT[(size_t)(nB + row)*CHANNELS + c]);
    }
    CP_COMMIT();
    #pragma unroll
    for (int q = 0; q < 4; q++) {
        int i = tid + q*256;
        int row = i >> 3, c = (i & 7) * 8;
        cp16b(&fsm[FK0 + row*72 + c], &kT[(size_t)row*CHANNELS + c]);
        int vr = i >> 4, vc = (i & 15) * 8;
        cp16b(&fsm[FV0 + vr*136 + vc], &vB[(size_t)vr*SPATIAL + vc]);
    }
    CP_COMMIT();

    float accO[8][4];
    #pragma unroll
    for (int i = 0; i < 8; i++)
        #pragma unroll
        for (int t = 0; t < 4; t++) accO[i][t] = 0.f;
    float mPrev0 = -1e30f, mPrev8 = -1e30f;
    float l0 = 0.f, l8 = 0.f;

    // ---- hoist Q fragments: loop-invariant across all m-tiles ----
    uint32_t qa[4][4];
    {
        CP_WAIT(1);          // Q group complete
        __syncthreads();
        uint32_t Qa = (uint32_t)__cvta_generic_to_shared(fsm + FQ) + n0*144 + aoff;
        #pragma unroll
        for (int ks = 0; ks < 4; ks++)
            ldm4(qa[ks], Qa + ks*32);
    }

    for (int it = 0; it < 8; it++) {
        int cur = it & 1;
        CP_WAIT(0);
        __syncthreads();   // data `it` ready; all warps done reading cur^1 buffers
        if (it < 7) {
            int m1 = (it+1)*128;
            uint16_t* Kn = fsm + (cur ? FK0 : FK1);
            uint16_t* Vn = fsm + (cur ? FV0 : FV1);
            #pragma unroll
            for (int q = 0; q < 4; q++) {
                int i = tid + q*256;
                int row = i >> 3, c = (i & 7) * 8;
                cp16b(&Kn[row*72 + c], &kT[(size_t)(m1 + row)*CHANNELS + c]);
                int vr = i >> 4, vc = (i & 15) * 8;
                cp16b(&Vn[vr*136 + vc], &vB[(size_t)vr*SPATIAL + m1 + vc]);
            }
            CP_COMMIT();
        }

        uint32_t Ka = (uint32_t)__cvta_generic_to_shared(fsm + (cur ? FK1 : FK0)) + boff;
        uint32_t Va = (uint32_t)__cvta_generic_to_shared(fsm + (cur ? FV1 : FV0)) + vboff;

        // ---- S = Q K^T (log2-domain, scale pre-folded) ----
        float accS[16][4];
        #pragma unroll
        for (int i = 0; i < 16; i++)
            #pragma unroll
            for (int t = 0; t < 4; t++) accS[i][t] = 0.f;
        #pragma unroll
        for (int ks = 0; ks < 4; ks++) {
            #pragma unroll
            for (int pp = 0; pp < 8; pp++) {
                uint32_t bb[4];
                ldm4(bb, Ka + pp*2304 + ks*32);
                mma16(accS[2*pp],   qa[ks], &bb[0]);
                mma16(accS[2*pp+1], qa[ks], &bb[2]);
            }
        }

        // ---- online softmax (exp2 domain) ----
        float tm0 = -1e30f, tm8 = -1e30f;
        #pragma unroll
        for (int ni = 0; ni < 16; ni++) {
            tm0 = fmaxf(tm0, fmaxf(accS[ni][0], accS[ni][1]));
            tm8 = fmaxf(tm8, fmaxf(accS[ni][2], accS[ni][3]));
        }
        tm0 = fmaxf(tm0, __shfl_xor_sync(0xffffffffu, tm0, 1));
        tm0 = fmaxf(tm0, __shfl_xor_sync(0xffffffffu, tm0, 2));
        tm8 = fmaxf(tm8, __shfl_xor_sync(0xffffffffu, tm8, 1));
        tm8 = fmaxf(tm8, __shfl_xor_sync(0xffffffffu, tm8, 2));

        float mNew0 = fmaxf(mPrev0, tm0);
        float mNew8 = fmaxf(mPrev8, tm8);
        float alpha0 = ex2(mPrev0 - mNew0);
        float alpha8 = ex2(mPrev8 - mNew8);
        mPrev0 = mNew0; mPrev8 = mNew8;

        uint32_t pk0[16], pk8[16];
        float sum0 = 0.f, sum8 = 0.f;
        #pragma unroll
        for (int ni = 0; ni < 16; ni++) {
            float p0 = ex2(accS[ni][0] - mNew0);
            float p1 = ex2(accS[ni][1] - mNew0);
            float p2 = ex2(accS[ni][2] - mNew8);
            float p3 = ex2(accS[ni][3] - mNew8);
            sum0 += p0 + p1; sum8 += p2 + p3;
            pk0[ni] = packbf(p0, p1);
            pk8[ni] = packbf(p2, p3);
        }
        sum0 += __shfl_xor_sync(0xffffffffu, sum0, 1);
        sum0 += __shfl_xor_sync(0xffffffffu, sum0, 2);
        sum8 += __shfl_xor_sync(0xffffffffu, sum8, 1);
        sum8 += __shfl_xor_sync(0xffffffffu, sum8, 2);
        l0 = l0*alpha0 + sum0;
        l8 = l8*alpha8 + sum8;

        if (alpha0 != 1.0f) {
            #pragma unroll
            for (int ni = 0; ni < 8; ni++) {
                accO[ni][0] *= alpha0; accO[ni][1] *= alpha0;
            }
        }
        if (alpha8 != 1.0f) {
            #pragma unroll
            for (int ni = 0; ni < 8; ni++) {
                accO[ni][2] *= alpha8; accO[ni][3] *= alpha8;
            }
        }

        // ---- O += P V^T ----
        #pragma unroll
        for (int ks = 0; ks < 8; ks++) {
            uint32_t a[4] = { pk0[2*ks], pk8[2*ks], pk0[2*ks+1], pk8[2*ks+1] };
            #pragma unroll
            for (int pp = 0; pp < 4; pp++) {
                uint32_t bb[4];
                ldm4(bb, Va + pp*4352 + ks*32);
                mma16(accO[2*pp],   a, &bb[0]);
                mma16(accO[2*pp+1], a, &bb[2]);
            }
        }
    }

    // ---- finalize: bf16 store to aoT [p][c] ----
    float inv0 = 1.f / l0, inv8 = 1.f / l8;
    uint32_t* r0 = (uint32_t*)(aoT + (size_t)(nB + n0 + lq)*CHANNELS);
    uint32_t* r8 = (uint32_t*)(aoT + (size_t)(nB + n0 + lq + 8)*CHANNELS);
    #pragma unroll
    for (int ni = 0; ni < 8; ni++) {
        r0[ni*4 + lr] = packbf(accO[ni][0]*inv0, accO[ni][1]*inv0);
        r8[ni*4 + lr] = packbf(accO[ni][2]*inv8, accO[ni][3]*inv8);
    }
}

// ============================================================================
extern "C" void kernel_launch(void* const* d_in, const int* in_sizes, int n_in,
                              void* d_out, int out_size) {
    const float* x  = (const float*)d_in[0];
    const float* nw = (const float*)d_in[1];
    const float* nb = (const float*)d_in[2];
    const float* qw = (const float*)d_in[3];
    const float* qb = (const float*)d_in[4];
    const float* kw = (const float*)d_in[5];
    const float* kb = (const float*)d_in[6];
    const float* vw = (const float*)d_in[7];
    const float* vb = (const float*)d_in[8];
    const float* pw = (const float*)d_in[9];
    const float* pb = (const float*)d_in[10];
    float* out = (float*)d_out;
    (void)in_sizes; (void)n_in; (void)out_size;

    cudaFuncSetAttribute(flash_bf,
                         cudaFuncAttributeMaxDynamicSharedMemorySize, (int)FL_SMEM);
    cudaFuncSetAttribute(conv_qkv_bf,
                         cudaFuncAttributeMaxDynamicSharedMemorySize, (int)CONV_SMEM);
    cudaFuncSetAttribute(conv_proj_bf,
                         cudaFuncAttributeMaxDynamicSharedMemorySize, (int)CONV_SMEM);

    wprep<<<2056, 256>>>(qw, kw, vw, pw, qb, kb, vb, pb);
    gnT_kernel<<<BATCH*8, 512>>>(x, nw, nb);

    conv_qkv_bf<<<dim3(SPATIAL/128, 12, BATCH), 256, CONV_SMEM>>>();

    flash_bf<<<dim3(SPATIAL/128, NBH), 256, FL_SMEM>>>();

    conv_proj_bf<<<dim3(SPATIAL/128, CHANNELS/128, BATCH), 256, CONV_SMEM>>>(x, out);
}

// round 17
// speedup vs baseline: 1.0417x; 1.0417x over previous
#include <cuda_runtime.h>
#include <cstdint>

#define BATCH    8
#define CHANNELS 512
#define SPATIAL  1024
#define NHEADS   8
#define HDIM     64
#define GCH      64
#define NBH      (BATCH*NHEADS)
#define BC       (CHANNELS*SPATIAL)

// -------- scratch --------
__device__ uint16_t g_xnT[BATCH*BC];             // bf16 [b][p][c]
__device__ uint16_t g_qT [BATCH*BC];             // bf16 [b][p][c] (scale*log2e folded)
__device__ uint16_t g_kT [BATCH*BC];             // bf16 [b][p][c]
__device__ uint16_t g_v  [BATCH*BC];             // bf16 [b][c][p]
__device__ uint16_t g_aoT[BATCH*BC];             // bf16 [b][p][c]
__device__ uint16_t g_w[4][CHANNELS*CHANNELS];   // bf16 [o][c]
__device__ float    g_b[4][CHANNELS];

// ---------------- helpers ----------------
__device__ __forceinline__ uint32_t packbf(float lo, float hi) {
    uint32_t r;
    asm("cvt.rn.bf16x2.f32 %0, %1, %2;" : "=r"(r) : "f"(hi), "f"(lo));
    return r;
}
__device__ __forceinline__ uint16_t bf16u(float x) {
    uint16_t u;
    asm("cvt.rn.bf16.f32 %0, %1;" : "=h"(u) : "f"(x));
    return u;
}
__device__ __forceinline__ float ex2(float x) {
    float r;
    asm("ex2.approx.ftz.f32 %0, %1;" : "=f"(r) : "f"(x));
    return r;
}
__device__ __forceinline__ void mma16(float* c, const uint32_t* a, const uint32_t* b) {
    asm volatile("mma.sync.aligned.m16n8k16.row.col.f32.bf16.bf16.f32 "
        "{%0,%1,%2,%3}, {%4,%5,%6,%7}, {%8,%9}, {%0,%1,%2,%3};"
        : "+f"(c[0]), "+f"(c[1]), "+f"(c[2]), "+f"(c[3])
        : "r"(a[0]), "r"(a[1]), "r"(a[2]), "r"(a[3]), "r"(b[0]), "r"(b[1]));
}
__device__ __forceinline__ void ldm4(uint32_t* r, uint32_t saddr) {
    asm volatile("ldmatrix.sync.aligned.m8n8.x4.shared.b16 {%0,%1,%2,%3}, [%4];"
        : "=r"(r[0]), "=r"(r[1]), "=r"(r[2]), "=r"(r[3]) : "r"(saddr));
}
__device__ __forceinline__ void cp16b(uint16_t* s, const uint16_t* g) {
    uint32_t sa = (uint32_t)__cvta_generic_to_shared(s);
    asm volatile("cp.async.cg.shared.global [%0], [%1], 16;" :: "r"(sa), "l"(g));
}
#define CP_COMMIT() asm volatile("cp.async.commit_group;" ::: "memory")
#define CP_WAIT(N)  asm volatile("cp.async.wait_group %0;" :: "n"(N) : "memory")

#define QSCALE (0.125f * 1.44269504f)

// ============================================================================
// Fused GroupNorm+transpose (blocks 0..63) and weight prep (blocks 64..323).
// ============================================================================
#define GN_BLOCKS  (BATCH*8)
#define WP_BLOCKS  260
#define WP_STRIDE  (WP_BLOCKS*512)

__global__ __launch_bounds__(512) void gnT_wprep_kernel(
        const float* __restrict__ x, const float* __restrict__ w, const float* __restrict__ bgn,
        const float* __restrict__ qw, const float* __restrict__ kw,
        const float* __restrict__ vw, const float* __restrict__ pw,
        const float* __restrict__ qb, const float* __restrict__ kb,
        const float* __restrict__ vb, const float* __restrict__ pb) {
    int tid = threadIdx.x;

    if (blockIdx.x >= GN_BLOCKS) {
        // ---- weight/bias prep ----
        int bid2 = blockIdx.x - GN_BLOCKS;
        for (int g = bid2*512 + tid; g < 4*131072 + 2048; g += WP_STRIDE) {
            if (g < 4*131072) {
                int m = g >> 17, r = g & 131071;
                const float* src = m == 0 ? qw : m == 1 ? kw : m == 2 ? vw : pw;
                float sc = (m == 0) ? QSCALE : 1.f;
                float2 v = *(const float2*)&src[(size_t)r*2];
                ((uint32_t*)g_w[m])[r] = packbf(v.x*sc, v.y*sc);
            } else {
                int gb = g - 4*131072;
                int m = gb >> 9, o = gb & 511;
                const float* src = m == 0 ? qb : m == 1 ? kb : m == 2 ? vb : pb;
                g_b[m][o] = src[o] * ((m == 0) ? QSCALE : 1.f);
            }
        }
        return;
    }

    // ---- GroupNorm + transpose ----
    int bg = blockIdx.x;
    int b = bg >> 3, g = bg & 7;
    size_t base = (size_t)(b*CHANNELS + g*GCH) * SPATIAL;
    const float4* x4 = (const float4*)(x + base);

    float s = 0.f, ss = 0.f;
    for (int i = tid; i < GCH*SPATIAL/4; i += 512) {
        float4 v = x4[i];
        s  += v.x + v.y + v.z + v.w;
        ss += v.x*v.x + v.y*v.y + v.z*v.z + v.w*v.w;
    }
    __shared__ float rs[512], rq[512];
    rs[tid] = s; rq[tid] = ss;
    __syncthreads();
    for (int o = 256; o > 0; o >>= 1) {
        if (tid < o) { rs[tid] += rs[tid+o]; rq[tid] += rq[tid+o]; }
        __syncthreads();
    }
    float mu  = rs[0] * (1.f/65536.f);
    float var = rq[0] * (1.f/65536.f) - mu*mu;
    float rstd = rsqrtf(var + 1e-5f);

    __shared__ float tile[2][GCH][33];
    int cl = tid >> 3, p4 = (tid & 7) * 4;
    float wc = w[g*GCH + cl] * rstd;
    float bc = bgn[g*GCH + cl] - mu*wc;
    int pw2 = tid >> 4, c4 = (tid & 15) * 4;

    {
        float4 v = *(const float4*)&x[base + (size_t)cl*SPATIAL + p4];
        tile[0][cl][p4    ] = v.x*wc + bc;
        tile[0][cl][p4 + 1] = v.y*wc + bc;
        tile[0][cl][p4 + 2] = v.z*wc + bc;
        tile[0][cl][p4 + 3] = v.w*wc + bc;
    }
    for (int pt = 0; pt < 32; pt++) {
        int cur = pt & 1;
        __syncthreads();
        if (pt < 31) {
            int pB1 = (pt+1) * 32;
            float4 v = *(const float4*)&x[base + (size_t)cl*SPATIAL + pB1 + p4];
            tile[cur^1][cl][p4    ] = v.x*wc + bc;
            tile[cur^1][cl][p4 + 1] = v.y*wc + bc;
            tile[cur^1][cl][p4 + 2] = v.z*wc + bc;
            tile[cur^1][cl][p4 + 3] = v.w*wc + bc;
        }
        int pB = pt * 32;
        uint2 o;
        o.x = packbf(tile[cur][c4  ][pw2], tile[cur][c4+1][pw2]);
        o.y = packbf(tile[cur][c4+2][pw2], tile[cur][c4+3][pw2]);
        *(uint2*)&g_xnT[((size_t)b*SPATIAL + pB + pw2)*CHANNELS + g*GCH + c4] = o;
    }
}

// ============================================================================
// Conv1x1 bf16 m16n8k16 + ldmatrix, Kt=64, R10 double-buffered pipeline.
// ============================================================================
#define CSTG 9216
#define CONV_SMEM (4*CSTG*2)   // 73728 B

__device__ __forceinline__ void conv_stage_bf(uint16_t* sA, uint16_t* sB,
                                              const uint16_t* W, const uint16_t* Xt,
                                              int k0, int tid) {
    #pragma unroll
    for (int q = 0; q < 4; q++) {
        int i = tid + q*256;
        int row = i >> 3, c = (i & 7) * 8;
        cp16b(&sA[row*72 + c], &W[(size_t)row*CHANNELS + k0 + c]);
    }
    #pragma unroll
    for (int q = 0; q < 4; q++) {
        int i = tid + q*256;
        int row = i >> 3, c = (i & 7) * 8;
        cp16b(&sB[row*72 + c], &Xt[(size_t)row*CHANNELS + k0 + c]);
    }
}

__device__ __forceinline__ void conv_core_bf(const uint16_t* __restrict__ W,
                                             const float* __restrict__ bias,
                                             const uint16_t* __restrict__ Xt,
                                             int mode,
                                             uint16_t* __restrict__ outT,
                                             uint16_t* __restrict__ outD,
                                             float* __restrict__ outF,
                                             const float* __restrict__ resid) {
    extern __shared__ __align__(16) uint16_t csm[];
    int tid = threadIdx.x, lane = tid & 31, wid = tid >> 5;
    int wy = wid & 3, wx = wid >> 2;
    int lq = lane >> 2, lr = lane & 3;

    uint32_t aoff = (lane & 15)*144 + (lane >> 4)*16;
    uint32_t boff = (lane & 7)*144 + ((lane >> 3) & 1)*16 + (lane >> 4)*1152;

    float acc[2][8][4];
    #pragma unroll
    for (int i = 0; i < 2; i++)
        #pragma unroll
        for (int j = 0; j < 8; j++)
            #pragma unroll
            for (int t = 0; t < 4; t++) acc[i][j][t] = 0.f;

    conv_stage_bf(csm, csm + 2*CSTG, W, Xt, 0, tid);
    CP_COMMIT();

    for (int it = 0; it < 8; it++) {
        int cur = it & 1;
        if (it < 7) {
            conv_stage_bf(csm + (cur^1)*CSTG, csm + (2 + (cur^1))*CSTG,
                          W, Xt, (it+1)*64, tid);
            CP_COMMIT();
            CP_WAIT(1);
        } else {
            CP_WAIT(0);
        }
        __syncthreads();

        uint32_t sAa = (uint32_t)__cvta_generic_to_shared(csm + cur*CSTG);
        uint32_t sBa = (uint32_t)__cvta_generic_to_shared(csm + (2+cur)*CSTG);
        #pragma unroll
        for (int ks = 0; ks < 4; ks++) {
            uint32_t a[2][4], b[4][4];
            #pragma unroll
            for (int mi = 0; mi < 2; mi++)
                ldm4(a[mi], sAa + (wy*32 + mi*16)*144 + ks*32 + aoff);
            #pragma unroll
            for (int pp = 0; pp < 4; pp++)
                ldm4(b[pp], sBa + (wx*64 + pp*16)*144 + ks*32 + boff);
            #pragma unroll
            for (int mi = 0; mi < 2; mi++)
                #pragma unroll
                for (int pp = 0; pp < 4; pp++) {
                    mma16(acc[mi][2*pp],   a[mi], &b[pp][0]);
                    mma16(acc[mi][2*pp+1], a[mi], &b[pp][2]);
                }
        }
        __syncthreads();
    }

    if (mode == 2) {
        #pragma unroll
        for (int mi = 0; mi < 2; mi++) {
            int o0 = wy*32 + mi*16 + lq;
            float bi0 = bias[o0], bi8 = bias[o0+8];
            #pragma unroll
            for (int ni = 0; ni < 8; ni++) {
                int p = wx*64 + ni*8 + lr*2;
                size_t off0 = (size_t)o0*SPATIAL + p;
                size_t off8 = (size_t)(o0+8)*SPATIAL + p;
                float2 r0 = make_float2(acc[mi][ni][0] + bi0, acc[mi][ni][1] + bi0);
                float2 r8 = make_float2(acc[mi][ni][2] + bi8, acc[mi][ni][3] + bi8);
                float2 v0 = *(const float2*)&resid[off0];
                float2 v8 = *(const float2*)&resid[off8];
                r0.x += v0.x; r0.y += v0.y;
                r8.x += v8.x; r8.y += v8.y;
                *(float2*)&outF[off0] = r0;
                *(float2*)&outF[off8] = r8;
            }
        }
    } else if (mode == 1) {
        #pragma unroll
        for (int mi = 0; mi < 2; mi++) {
            int o0 = wy*32 + mi*16 + lq;
            float bi0 = bias[o0], bi8 = bias[o0+8];
            uint32_t* r0 = (uint32_t*)(outD + (size_t)o0*SPATIAL);
            uint32_t* r8 = (uint32_t*)(outD + (size_t)(o0+8)*SPATIAL);
            #pragma unroll
            for (int ni = 0; ni < 8; ni++) {
                int pc = wx*32 + ni*4 + lr;
                r0[pc] = packbf(acc[mi][ni][0] + bi0, acc[mi][ni][1] + bi0);
                r8[pc] = packbf(acc[mi][ni][2] + bi8, acc[mi][ni][3] + bi8);
            }
        }
    } else {
        uint16_t* Ts = csm;   // [128 p][136]
        #pragma unroll
        for (int mi = 0; mi < 2; mi++) {
            int o0 = wy*32 + mi*16 + lq;
            float bi0 = bias[o0], bi8 = bias[o0+8];
            #pragma unroll
            for (int ni = 0; ni < 8; ni++) {
                int p = wx*64 + ni*8 + lr*2;
                Ts[(p  )*136 + o0    ] = bf16u(acc[mi][ni][0] + bi0);
                Ts[(p+1)*136 + o0    ] = bf16u(acc[mi][ni][1] + bi0);
                Ts[(p  )*136 + o0 + 8] = bf16u(acc[mi][ni][2] + bi8);
                Ts[(p+1)*136 + o0 + 8] = bf16u(acc[mi][ni][3] + bi8);
            }
        }
        __syncthreads();
        #pragma unroll
        for (int q = 0; q < 8; q++) {
            int i = tid + q*256;
            int p = i >> 4, c = (i & 15) * 8;
            *(uint4*)&outT[(size_t)p*CHANNELS + c] = *(uint4*)&Ts[p*136 + c];
        }
    }
}

__global__ __launch_bounds__(256, 2) void conv_qkv_bf() {
    int b = blockIdx.z;
    int sel = blockIdx.y >> 2;
    int oB = (blockIdx.y & 3) * 128;
    int pB = blockIdx.x * 128;
    const uint16_t* W = g_w[sel] + (size_t)oB*CHANNELS;
    const float* bias = g_b[sel] + oB;
    const uint16_t* Xt = g_xnT + ((size_t)b*SPATIAL + pB)*CHANNELS;
    if (sel == 2) {
        conv_core_bf(W, bias, Xt, 1, nullptr,
                     g_v + (size_t)b*BC + (size_t)oB*SPATIAL + pB, nullptr, nullptr);
    } else {
        uint16_t* gT = (sel == 0) ? g_qT : g_kT;
        conv_core_bf(W, bias, Xt, 0,
                     gT + (size_t)b*BC + (size_t)pB*CHANNELS + oB,
                     nullptr, nullptr, nullptr);
    }
}

__global__ __launch_bounds__(256, 2) void conv_proj_bf(const float* __restrict__ x,
                                                       float* __restrict__ out) {
    int b = blockIdx.z, oB = blockIdx.y*128, pB = blockIdx.x*128;
    conv_core_bf(g_w[3] + (size_t)oB*CHANNELS, g_b[3] + oB,
                 g_aoT + ((size_t)b*SPATIAL + pB)*CHANNELS, 2,
                 nullptr, nullptr,
                 out + (size_t)b*BC + (size_t)oB*SPATIAL + pB,
                 x + (size_t)b*BC + (size_t)oB*SPATIAL + pB);
}

// ============================================================================
// Flash bf16 (R14 config): m-tile 128, exp2 softmax, alpha-skip, 1 barrier/iter.
// smem halves: Q[128][72] | K0[128][72] | K1 | V0[64][136] | V1
// ============================================================================
#define FQ  0
#define FK0 9216
#define FK1 18432
#define FV0 27648
#define FV1 36352
#define FL_SMEM (45056 * 2)   // 90112 B

__global__ __launch_bounds__(256, 2) void flash_bf() {
    extern __shared__ __align__(16) uint16_t fsm[];
    int nB = blockIdx.x * 128;
    int bh = blockIdx.y;
    int b = bh >> 3, h = bh & 7;
    const uint16_t* qT = g_qT + (size_t)b*BC + h*HDIM;
    const uint16_t* kT = g_kT + (size_t)b*BC + h*HDIM;
    const uint16_t* vB = g_v  + (size_t)b*BC + (size_t)h*HDIM*SPATIAL;
    uint16_t* aoT      = g_aoT + (size_t)b*BC + h*HDIM;

    int tid = threadIdx.x, lane = tid & 31, wid = tid >> 5;
    int lq = lane >> 2, lr = lane & 3;
    int n0 = wid * 16;

    uint32_t aoff  = (lane & 15)*144 + (lane >> 4)*16;
    uint32_t boff  = (lane & 7)*144 + ((lane >> 3) & 1)*16 + (lane >> 4)*1152;
    uint32_t vboff = (lane & 7)*272 + ((lane >> 3) & 1)*16 + (lane >> 4)*2176;

    // stage Q + K0/V0
    #pragma unroll
    for (int q = 0; q < 4; q++) {
        int i = tid + q*256;
        int row = i >> 3, c = (i & 7) * 8;
        cp16b(&fsm[FQ + row*72 + c], &qT[(size_t)(nB + row)*CHANNELS + c]);
    }
    #pragma unroll
    for (int q = 0; q < 4; q++) {
        int i = tid + q*256;
        int row = i >> 3, c = (i & 7) * 8;
        cp16b(&fsm[FK0 + row*72 + c], &kT[(size_t)row*CHANNELS + c]);
        int vr = i >> 4, vc = (i & 15) * 8;
        cp16b(&fsm[FV0 + vr*136 + vc], &vB[(size_t)vr*SPATIAL + vc]);
    }
    CP_COMMIT();

    float accO[8][4];
    #pragma unroll
    for (int i = 0; i < 8; i++)
        #pragma unroll
        for (int t = 0; t < 4; t++) accO[i][t] = 0.f;
    float mPrev0 = -1e30f, mPrev8 = -1e30f;
    float l0 = 0.f, l8 = 0.f;

    uint32_t Qa = (uint32_t)__cvta_generic_to_shared(fsm + FQ) + n0*144 + aoff;

    for (int it = 0; it < 8; it++) {
        int cur = it & 1;
        CP_WAIT(0);
        __syncthreads();
        if (it < 7) {
            int m1 = (it+1)*128;
            uint16_t* Kn = fsm + (cur ? FK0 : FK1);
            uint16_t* Vn = fsm + (cur ? FV0 : FV1);
            #pragma unroll
            for (int q = 0; q < 4; q++) {
                int i = tid + q*256;
                int row = i >> 3, c = (i & 7) * 8;
                cp16b(&Kn[row*72 + c], &kT[(size_t)(m1 + row)*CHANNELS + c]);
                int vr = i >> 4, vc = (i & 15) * 8;
                cp16b(&Vn[vr*136 + vc], &vB[(size_t)vr*SPATIAL + m1 + vc]);
            }
            CP_COMMIT();
        }

        uint32_t Ka = (uint32_t)__cvta_generic_to_shared(fsm + (cur ? FK1 : FK0)) + boff;
        uint32_t Va = (uint32_t)__cvta_generic_to_shared(fsm + (cur ? FV1 : FV0)) + vboff;

        // ---- S = Q K^T (log2-domain, scale pre-folded) ----
        float accS[16][4];
        #pragma unroll
        for (int i = 0; i < 16; i++)
            #pragma unroll
            for (int t = 0; t < 4; t++) accS[i][t] = 0.f;
        #pragma unroll
        for (int ks = 0; ks < 4; ks++) {
            uint32_t a[4];
            ldm4(a, Qa + ks*32);
            #pragma unroll
            for (int pp = 0; pp < 8; pp++) {
                uint32_t bb[4];
                ldm4(bb, Ka + pp*2304 + ks*32);
                mma16(accS[2*pp],   a, &bb[0]);
                mma16(accS[2*pp+1], a, &bb[2]);
            }
        }

        // ---- online softmax (exp2 domain) ----
        float tm0 = -1e30f, tm8 = -1e30f;
        #pragma unroll
        for (int ni = 0; ni < 16; ni++) {
            tm0 = fmaxf(tm0, fmaxf(accS[ni][0], accS[ni][1]));
            tm8 = fmaxf(tm8, fmaxf(accS[ni][2], accS[ni][3]));
        }
        tm0 = fmaxf(tm0, __shfl_xor_sync(0xffffffffu, tm0, 1));
        tm0 = fmaxf(tm0, __shfl_xor_sync(0xffffffffu, tm0, 2));
        tm8 = fmaxf(tm8, __shfl_xor_sync(0xffffffffu, tm8, 1));
        tm8 = fmaxf(tm8, __shfl_xor_sync(0xffffffffu, tm8, 2));

        float mNew0 = fmaxf(mPrev0, tm0);
        float mNew8 = fmaxf(mPrev8, tm8);
        float alpha0 = ex2(mPrev0 - mNew0);
        float alpha8 = ex2(mPrev8 - mNew8);
        mPrev0 = mNew0; mPrev8 = mNew8;

        uint32_t pk0[16], pk8[16];
        float sum0 = 0.f, sum8 = 0.f;
        #pragma unroll
        for (int ni = 0; ni < 16; ni++) {
            float p0 = ex2(accS[ni][0] - mNew0);
            float p1 = ex2(accS[ni][1] - mNew0);
            float p2 = ex2(accS[ni][2] - mNew8);
            float p3 = ex2(accS[ni][3] - mNew8);
            sum0 += p0 + p1; sum8 += p2 + p3;
            pk0[ni] = packbf(p0, p1);
            pk8[ni] = packbf(p2, p3);
        }
        sum0 += __shfl_xor_sync(0xffffffffu, sum0, 1);
        sum0 += __shfl_xor_sync(0xffffffffu, sum0, 2);
        sum8 += __shfl_xor_sync(0xffffffffu, sum8, 1);
        sum8 += __shfl_xor_sync(0xffffffffu, sum8, 2);
        l0 = l0*alpha0 + sum0;
        l8 = l8*alpha8 + sum8;

        if (alpha0 != 1.0f) {
            #pragma unroll
            for (int ni = 0; ni < 8; ni++) {
                accO[ni][0] *= alpha0; accO[ni][1] *= alpha0;
            }
        }
        if (alpha8 != 1.0f) {
            #pragma unroll
            for (int ni = 0; ni < 8; ni++) {
                accO[ni][2] *= alpha8; accO[ni][3] *= alpha8;
            }
        }

        // ---- O += P V^T ----
        #pragma unroll
        for (int ks = 0; ks < 8; ks++) {
            uint32_t a[4] = { pk0[2*ks], pk8[2*ks], pk0[2*ks+1], pk8[2*ks+1] };
            #pragma unroll
            for (int pp = 0; pp < 4; pp++) {
                uint32_t bb[4];
                ldm4(bb, Va + pp*4352 + ks*32);
                mma16(accO[2*pp],   a, &bb[0]);
                mma16(accO[2*pp+1], a, &bb[2]);
            }
        }
    }

    // ---- finalize: bf16 store to aoT [p][c] ----
    float inv0 = 1.f / l0, inv8 = 1.f / l8;
    uint32_t* r0 = (uint32_t*)(aoT + (size_t)(nB + n0 + lq)*CHANNELS);
    uint32_t* r8 = (uint32_t*)(aoT + (size_t)(nB + n0 + lq + 8)*CHANNELS);
    #pragma unroll
    for (int ni = 0; ni < 8; ni++) {
        r0[ni*4 + lr] = packbf(accO[ni][0]*inv0, accO[ni][1]*inv0);
        r8[ni*4 + lr] = packbf(accO[ni][2]*inv8, accO[ni][3]*inv8);
    }
}

// ============================================================================
extern "C" void kernel_launch(void* const* d_in, const int* in_sizes, int n_in,
                              void* d_out, int out_size) {
    const float* x  = (const float*)d_in[0];
    const float* nw = (const float*)d_in[1];
    const float* nb = (const float*)d_in[2];
    const float* qw = (const float*)d_in[3];
    const float* qb = (const float*)d_in[4];
    const float* kw = (const float*)d_in[5];
    const float* kb = (const float*)d_in[6];
    const float* vw = (const float*)d_in[7];
    const float* vb = (const float*)d_in[8];
    const float* pw = (const float*)d_in[9];
    const float* pb = (const float*)d_in[10];
    float* out = (float*)d_out;
    (void)in_sizes; (void)n_in; (void)out_size;

    cudaFuncSetAttribute(flash_bf,
                         cudaFuncAttributeMaxDynamicSharedMemorySize, (int)FL_SMEM);
    cudaFuncSetAttribute(conv_qkv_bf,
                         cudaFuncAttributeMaxDynamicSharedMemorySize, (int)CONV_SMEM);
    cudaFuncSetAttribute(conv_proj_bf,
                         cudaFuncAttributeMaxDynamicSharedMemorySize, (int)CONV_SMEM);

    gnT_wprep_kernel<<<GN_BLOCKS + WP_BLOCKS, 512>>>(x, nw, nb,
                                                     qw, kw, vw, pw,
                                                     qb, kb, vb, pb);

    conv_qkv_bf<<<dim3(SPATIAL/128, 12, BATCH), 256, CONV_SMEM>>>();

    flash_bf<<<dim3(SPATIAL/128, NBH), 256, FL_SMEM>>>();

    conv_proj_bf<<<dim3(SPATIAL/128, CHANNELS/128, BATCH), 256, CONV_SMEM>>>(x, out);
}